// round 1
// baseline (speedup 1.0000x reference)
#include <cuda_runtime.h>
#include <math.h>

// Problem constants
#define BATCH   64
#define MAXN    128
#define GH      64
#define GW      32
#define NPTS    2048        // GH*GW
#define NSPLIT  8
#define CHUNK   16          // MAXN / NSPLIT
#define NTHREADS 256
#define PPT     8           // NPTS / NTHREADS

// Partial accumulators: [BATCH][NSPLIT][NPTS] complex (float2) = 8 MB
__device__ float2 g_partial[BATCH * NSPLIT * NPTS];

// pos_w[k] = float32(0.1 * (10^(1/30))^k), computed in double like numpy
__device__ __forceinline__ float pos_w_val(int k) {
    return (float)(0.1 * pow(10.0, (double)k / 30.0));
}

struct Tri { float xq, yq, dxr, dyr, dxs, dys, area; };

__global__ __launch_bounds__(NTHREADS)
void pfc_accum_kernel(const float* __restrict__ tris,
                      const int* __restrict__ lengths) {
    __shared__ float sWx[GH];
    __shared__ float sWy[GW];
    __shared__ Tri   sTri[CHUNK];

    const int tid = threadIdx.x;
    const int b   = blockIdx.x / NSPLIT;
    const int s   = blockIdx.x % NSPLIT;

    // Build frequency grid (once per block)
    if (tid < GH) {
        int h = tid;
        float v;
        if (h < 31)       v = -pos_w_val(30 - h);
        else if (h == 31) v = 0.0f;
        else if (h <= 62) v = pos_w_val(h - 32);
        else              v = 0.0f;           // padded row
        sWx[h] = v;
    } else if (tid < GH + GW) {
        int w = tid - GH;
        sWy[w] = (w == 0) ? 0.0f : pos_w_val(w - 1);
    }

    // Triangle chunk for this block
    const int len = lengths[b];
    const int t0  = s * CHUNK;
    const int t1  = min(len, t0 + CHUNK);
    const int ntri = (t1 > t0) ? (t1 - t0) : 0;

    if (tid < CHUNK) {
        int t = t0 + tid;
        if (t < t1) {
            const float* p = tris + (size_t)(b * MAXN + t) * 6;
            float xq = p[0], yq = p[1];
            float xr = p[2], yr = p[3];
            float xs = p[4], ys = p[5];
            float det = xq * (yr - ys) + xr * (ys - yq) + xs * (yq - yr);
            Tri tr;
            tr.xq = xq; tr.yq = yq;
            tr.dxr = xr - xq; tr.dyr = yr - yq;
            tr.dxs = xs - xr; tr.dys = ys - yr;
            tr.area = fabsf(0.5f * det);
            sTri[tid] = tr;
        }
    }
    __syncthreads();

    float U[PPT], V[PPT], accre[PPT], accim[PPT];
#pragma unroll
    for (int k = 0; k < PPT; k++) {
        int p = tid + k * NTHREADS;
        U[k] = sWx[p >> 5];
        V[k] = sWy[p & 31];
        accre[k] = 0.0f; accim[k] = 0.0f;
    }

    const float TWO_PI   = 6.28318530717958648f;                 // rounds to float32(2*pi)
    const float FOUR_PI2 = 4.0f * 3.14159274101257324f * 3.14159274101257324f;

    for (int j = 0; j < ntri; j++) {
        const float xq  = sTri[j].xq,  yq  = sTri[j].yq;
        const float dxr = sTri[j].dxr, dyr = sTri[j].dyr;
        const float dxs = sTri[j].dxs, dys = sTri[j].dys;
        const float area = sTri[j].area;
#pragma unroll
        for (int k = 0; k < PPT; k++) {
            const float u = U[k], v = V[k];
            const float U_ = u * dxr + v * dyr;
            const float V_ = u * dxs + v * dys;
            const float S  = U_ + V_;

            const bool zero = (U_ == 0.0f) && (V_ == 0.0f);
            if (zero) { accre[k] += area; continue; }
            const bool diag = (S  == 0.0f);
            const bool um   = (U_ == 0.0f);
            const bool vm   = (V_ == 0.0f);
            const bool norm = !(diag || um || vm);

            float su, cu, sv, cv, s0, c0;
            sincosf(-TWO_PI * U_, &su, &cu);
            sincosf(-TWO_PI * V_, &sv, &cv);
            sincosf(-TWO_PI * (u * xq + v * yq), &s0, &c0);

            float part1, p2re, p2im;
            if (norm) {
                part1 = 1.0f / (FOUR_PI2 * U_ * V_ * S);
                // base_uv = base_u * base_v
                float cuv = cu * cv - su * sv;
                float suv = su * cv + cu * sv;
                p2re = -U_ * cuv + S * cu - V_;
                p2im = -U_ * suv + S * su;
            } else if (diag) {
                part1 = -1.0f / (FOUR_PI2 * U_ * U_);
                p2re = cu - 1.0f;
                p2im = su + TWO_PI * U_;
            } else if (um) {
                part1 = -1.0f / (FOUR_PI2 * V_ * V_);
                p2re = cv - 1.0f;
                p2im = sv + TWO_PI * V_;
            } else { // vm
                part1 = 1.0f / (FOUR_PI2 * U_ * U_);
                float t = TWO_PI * U_;
                p2re = cu - t * su - 1.0f;
                p2im = su + t * cu;
            }
            const float scale = 2.0f * area * part1;
            accre[k] += scale * (p2re * c0 - p2im * s0);
            accim[k] += scale * (p2re * s0 + p2im * c0);
        }
    }

#pragma unroll
    for (int k = 0; k < PPT; k++) {
        int p = tid + k * NTHREADS;
        g_partial[(b * NSPLIT + s) * NPTS + p] = make_float2(accre[k], accim[k]);
    }
}

__global__ __launch_bounds__(256)
void pfc_finalize_kernel(float* __restrict__ out) {
    const int idx = blockIdx.x * blockDim.x + threadIdx.x;   // 0 .. BATCH*NPTS-1
    if (idx >= BATCH * NPTS) return;
    const int b = idx / NPTS;
    const int p = idx % NPTS;
    const int h = p >> 5;

    float re = 0.0f, im = 0.0f;
#pragma unroll
    for (int s = 0; s < NSPLIT; s++) {
        float2 v = g_partial[(b * NSPLIT + s) * NPTS + p];
        re += v.x; im += v.y;
    }

    float mag, phase;
    const float m2 = re * re + im * im;
    if (h == GH - 1 || m2 == 0.0f) {      // padded row, or zero total
        mag = 0.0f; phase = 0.0f;         // angle(0) = atan2(0, 1) = 0
    } else {
        mag   = log1pf(sqrtf(m2));
        phase = atan2f(im, re);
    }
    out[idx] = mag;                        // mag  block: [B,1,GH,GW]
    out[BATCH * NPTS + idx] = phase;       // phase block: [B,1,GH,GW]
}

extern "C" void kernel_launch(void* const* d_in, const int* in_sizes, int n_in,
                              void* d_out, int out_size) {
    const float* tris    = (const float*)d_in[0];   // [64,128,3,2] f32
    const int*   lengths = (const int*)d_in[1];     // [64] i32
    float* out = (float*)d_out;                     // 262144 f32: mag then phase

    pfc_accum_kernel<<<BATCH * NSPLIT, NTHREADS>>>(tris, lengths);
    pfc_finalize_kernel<<<(BATCH * NPTS + 255) / 256, 256>>>(out);
}

// round 2
// speedup vs baseline: 2.0194x; 2.0194x over previous
#include <cuda_runtime.h>
#include <math.h>

#define BATCH   64
#define MAXN    128
#define GH      64
#define GW      32
#define NPTS    2048        // GH*GW
#define NSPLIT  8
#define CHUNK   16          // MAXN / NSPLIT
#define NTHREADS 256
#define PPT     8           // NPTS / NTHREADS

// Partial accumulators: [BATCH][NSPLIT][NPTS] complex (float2) = 8 MB
__device__ float2 g_partial[BATCH * NSPLIT * NPTS];

// pos_w[k] = float32(0.1 * (10^(1/30))^k), computed in double like numpy
__device__ __forceinline__ float pos_w_val(int k) {
    return (float)(0.1 * pow(10.0, (double)k / 30.0));
}

struct Tri { float xq, yq, dxr, dyr, dxs, dys, area; };

__global__ __launch_bounds__(NTHREADS)
void pfc_accum_kernel(const float* __restrict__ tris,
                      const int* __restrict__ lengths) {
    __shared__ float sWx[GH];
    __shared__ float sWy[GW];
    __shared__ Tri   sTri[CHUNK];
    // Per-triangle factored tables: row (h) and col (w) components of the
    // three complex exponentials.  .x = linear term (Ua/Va), .y = cos, .z = sin
    __shared__ float4 sRowU[GH], sRowV[GH];
    __shared__ float2 sRowP[GH];
    __shared__ float4 sColU[GW], sColV[GW];
    __shared__ float2 sColP[GW];

    const int tid = threadIdx.x;
    const int b   = blockIdx.x >> 3;
    const int s   = blockIdx.x & 7;

    // Build frequency grid (once per block)
    if (tid < GH) {
        int h = tid;
        float v;
        if (h < 31)       v = -pos_w_val(30 - h);
        else if (h == 31) v = 0.0f;
        else if (h <= 62) v = pos_w_val(h - 32);
        else              v = 0.0f;           // padded row
        sWx[h] = v;
    } else if (tid < GH + GW) {
        int w = tid - GH;
        sWy[w] = (w == 0) ? 0.0f : pos_w_val(w - 1);
    }

    const int len  = lengths[b];
    const int t0   = s * CHUNK;
    const int t1   = min(len, t0 + CHUNK);
    const int ntri = (t1 > t0) ? (t1 - t0) : 0;

    if (tid < CHUNK && tid < ntri) {
        const float* p = tris + (size_t)(b * MAXN + t0 + tid) * 6;
        float xq = p[0], yq = p[1];
        float xr = p[2], yr = p[3];
        float xs = p[4], ys = p[5];
        float det = xq * (yr - ys) + xr * (ys - yq) + xs * (yq - yr);
        Tri tr;
        tr.xq = xq; tr.yq = yq;
        tr.dxr = xr - xq; tr.dyr = yr - yq;
        tr.dxs = xs - xr; tr.dys = ys - yr;
        tr.area = fabsf(0.5f * det);
        sTri[tid] = tr;
    }
    __syncthreads();

    const float TWO_PI   = 6.28318530717958648f;
    const float FOUR_PI2 = 4.0f * 3.14159274101257324f * 3.14159274101257324f;

    const int w     = tid & 31;
    const int hbase = (tid >> 5) * PPT;

    float accre[PPT], accim[PPT];
#pragma unroll
    for (int k = 0; k < PPT; k++) { accre[k] = 0.0f; accim[k] = 0.0f; }

    for (int j = 0; j < ntri; j++) {
        const Tri tr = sTri[j];   // broadcast

        // ---- build factored tables for this triangle (288 sincos, coop) ----
        if (tid < 192) {
            int h = tid & 63;
            int which = tid >> 6;               // 0:rowU 1:rowV 2:rowP
            float wx = sWx[h];
            float a = wx * (which == 0 ? tr.dxr : (which == 1 ? tr.dxs : tr.xq));
            float sn, cs;
            sincosf(-TWO_PI * a, &sn, &cs);
            if (which == 0)      sRowU[h] = make_float4(a, cs, sn, 0.0f);
            else if (which == 1) sRowV[h] = make_float4(a, cs, sn, 0.0f);
            else                 sRowP[h] = make_float2(cs, sn);
        } else {
            int t  = tid - 192;                 // 0..63
            int ww = t & 31;
            int which = t >> 5;                 // 0:colU 1:colV
            float wy = sWy[ww];
            float a = wy * (which == 0 ? tr.dyr : tr.dys);
            float sn, cs;
            sincosf(-TWO_PI * a, &sn, &cs);
            if (which == 0) sColU[ww] = make_float4(a, cs, sn, 0.0f);
            else            sColV[ww] = make_float4(a, cs, sn, 0.0f);
        }
        if (tid < 32) {
            float a = sWy[tid] * tr.yq;
            float sn, cs;
            sincosf(-TWO_PI * a, &sn, &cs);
            sColP[tid] = make_float2(cs, sn);
        }
        __syncthreads();

        // ---- evaluate 8 points with no sincos ----
        const float area    = tr.area;
        const float twoArea = 2.0f * area;
        const float4 cU = sColU[w];
        const float4 cV = sColV[w];
        const float2 cP = sColP[w];

#pragma unroll
        for (int k = 0; k < PPT; k++) {
            const int h = hbase + k;            // uniform across the warp
            const float4 rU = sRowU[h];
            const float4 rV = sRowV[h];
            const float2 rP = sRowP[h];

            const float U_ = rU.x + cU.x;
            const float V_ = rV.x + cV.x;
            const float S  = U_ + V_;

            // three complex exponentials via products of unit phasors
            const float cu = rU.y * cU.y - rU.z * cU.z;
            const float su = rU.y * cU.z + rU.z * cU.y;
            const float cv = rV.y * cV.y - rV.z * cV.z;
            const float sv = rV.y * cV.z + rV.z * cV.y;
            const float c0 = rP.x * cP.x - rP.y * cP.y;
            const float s0 = rP.x * cP.y + rP.y * cP.x;

            float p2re, p2im, scale;
            if (U_ != 0.0f && V_ != 0.0f && S != 0.0f) {          // normal
                scale = __fdividef(twoArea, FOUR_PI2 * U_ * V_ * S);
                const float cuv = cu * cv - su * sv;
                const float suv = su * cv + cu * sv;
                p2re = -U_ * cuv + S * cu - V_;
                p2im = -U_ * suv + S * su;
            } else if (U_ == 0.0f && V_ == 0.0f) {                // zero
                accre[k] += area;
                continue;
            } else if (S == 0.0f) {                               // diag
                scale = -__fdividef(twoArea, FOUR_PI2 * U_ * U_);
                p2re = cu - 1.0f;
                p2im = su + TWO_PI * U_;
            } else if (U_ == 0.0f) {                              // u-mask
                scale = -__fdividef(twoArea, FOUR_PI2 * V_ * V_);
                p2re = cv - 1.0f;
                p2im = sv + TWO_PI * V_;
            } else {                                              // v-mask
                scale = __fdividef(twoArea, FOUR_PI2 * U_ * U_);
                const float t = TWO_PI * U_;
                p2re = cu - t * su - 1.0f;
                p2im = su + t * cu;
            }
            accre[k] += scale * (p2re * c0 - p2im * s0);
            accim[k] += scale * (p2re * s0 + p2im * c0);
        }
        __syncthreads();   // tables reused next triangle
    }

#pragma unroll
    for (int k = 0; k < PPT; k++) {
        const int p = (hbase + k) * GW + w;
        g_partial[(b * NSPLIT + s) * NPTS + p] = make_float2(accre[k], accim[k]);
    }
}

__global__ __launch_bounds__(256)
void pfc_finalize_kernel(float* __restrict__ out) {
    const int idx = blockIdx.x * blockDim.x + threadIdx.x;   // 0 .. BATCH*NPTS-1
    if (idx >= BATCH * NPTS) return;
    const int b = idx / NPTS;
    const int p = idx % NPTS;
    const int h = p >> 5;

    float re = 0.0f, im = 0.0f;
#pragma unroll
    for (int s = 0; s < NSPLIT; s++) {
        float2 v = g_partial[(b * NSPLIT + s) * NPTS + p];
        re += v.x; im += v.y;
    }

    float mag, phase;
    const float m2 = re * re + im * im;
    if (h == GH - 1 || m2 == 0.0f) {      // padded row, or zero total
        mag = 0.0f; phase = 0.0f;
    } else {
        mag   = log1pf(sqrtf(m2));
        phase = atan2f(im, re);
    }
    out[idx] = mag;                        // mag  block: [B,1,GH,GW]
    out[BATCH * NPTS + idx] = phase;       // phase block: [B,1,GH,GW]
}

extern "C" void kernel_launch(void* const* d_in, const int* in_sizes, int n_in,
                              void* d_out, int out_size) {
    const float* tris    = (const float*)d_in[0];   // [64,128,3,2] f32
    const int*   lengths = (const int*)d_in[1];     // [64] i32
    float* out = (float*)d_out;                     // 262144 f32: mag then phase

    pfc_accum_kernel<<<BATCH * NSPLIT, NTHREADS>>>(tris, lengths);
    pfc_finalize_kernel<<<(BATCH * NPTS + 255) / 256, 256>>>(out);
}

// round 3
// speedup vs baseline: 2.2798x; 1.1289x over previous
#include <cuda_runtime.h>
#include <math.h>

#define BATCH   64
#define MAXN    128
#define GH      64
#define GW      32
#define NPTS    2048        // GH*GW
#define NSPLIT  16
#define MAXCHUNK 8          // ceil(MAXN / NSPLIT)
#define NTHREADS 256
#define PPT     8           // NPTS / NTHREADS

// Partial accumulators: [BATCH][NSPLIT][NPTS] complex (float2) = 16 MB
__device__ float2 g_partial[BATCH * NSPLIT * NPTS];

// pos_w[k] = float32(0.1 * (10^(1/30))^k), computed in double like numpy
__device__ __forceinline__ float pos_w_val(int k) {
    return (float)(0.1 * pow(10.0, (double)k / 30.0));
}

struct Tri { float xq, yq, dxr, dyr, dxs, dys, area; };

__global__ __launch_bounds__(NTHREADS)
void pfc_accum_kernel(const float* __restrict__ tris,
                      const int* __restrict__ lengths) {
    __shared__ float sWx[GH];
    __shared__ float sWy[GW];
    __shared__ Tri   sTri[MAXCHUNK];
    // Double-buffered factored tables. .x = linear term, .y = cos, .z = sin
    __shared__ float4 sRowU[2][GH], sRowV[2][GH];
    __shared__ float2 sRowP[2][GH];
    __shared__ float4 sColU[2][GW], sColV[2][GW];
    __shared__ float2 sColP[2][GW];

    const int tid = threadIdx.x;
    const int b   = blockIdx.x >> 4;        // / NSPLIT
    const int s   = blockIdx.x & (NSPLIT - 1);

    // Build frequency grid (once per block)
    if (tid < GH) {
        int h = tid;
        float v;
        if (h < 31)       v = -pos_w_val(30 - h);
        else if (h == 31) v = 0.0f;
        else if (h <= 62) v = pos_w_val(h - 32);
        else              v = 0.0f;           // padded row
        sWx[h] = v;
    } else if (tid < GH + GW) {
        int w = tid - GH;
        sWy[w] = (w == 0) ? 0.0f : pos_w_val(w - 1);
    }

    const int len  = lengths[b];
    // interleaved assignment: this split owns triangles s, s+16, s+32, ...
    const int ntri = (len > s) ? ((len - 1 - s) / NSPLIT + 1) : 0;

    if (tid < MAXCHUNK && tid < ntri) {
        const int t = s + tid * NSPLIT;
        const float* p = tris + (size_t)(b * MAXN + t) * 6;
        float xq = p[0], yq = p[1];
        float xr = p[2], yr = p[3];
        float xs = p[4], ys = p[5];
        float det = xq * (yr - ys) + xr * (ys - yq) + xs * (yq - yr);
        Tri tr;
        tr.xq = xq; tr.yq = yq;
        tr.dxr = xr - xq; tr.dyr = yr - yq;
        tr.dxs = xs - xr; tr.dys = ys - yr;
        tr.area = fabsf(0.5f * det);
        sTri[tid] = tr;
    }
    __syncthreads();

    const float TWO_PI   = 6.28318530717958648f;
    const float FOUR_PI2 = 4.0f * 3.14159274101257324f * 3.14159274101257324f;

    const int w     = tid & 31;
    const int hbase = (tid >> 5) * PPT;

    float accre[PPT], accim[PPT];
#pragma unroll
    for (int k = 0; k < PPT; k++) { accre[k] = 0.0f; accim[k] = 0.0f; }

    for (int j = 0; j < ntri; j++) {
        const Tri tr = sTri[j];   // broadcast
        const int buf = j & 1;

        // ---- build factored tables for this triangle (288 sincos, coop) ----
        if (tid < 192) {
            int h = tid & 63;
            int which = tid >> 6;               // 0:rowU 1:rowV 2:rowP
            float wx = sWx[h];
            float a = wx * (which == 0 ? tr.dxr : (which == 1 ? tr.dxs : tr.xq));
            float sn, cs;
            sincosf(-TWO_PI * a, &sn, &cs);
            if (which == 0)      sRowU[buf][h] = make_float4(a, cs, sn, 0.0f);
            else if (which == 1) sRowV[buf][h] = make_float4(a, cs, sn, 0.0f);
            else                 sRowP[buf][h] = make_float2(cs, sn);
        } else {
            int t  = tid - 192;                 // 0..63
            int ww = t & 31;
            int which = t >> 5;                 // 0:colU 1:colV
            float wy = sWy[ww];
            float a = wy * (which == 0 ? tr.dyr : tr.dys);
            float sn, cs;
            sincosf(-TWO_PI * a, &sn, &cs);
            if (which == 0) sColU[buf][ww] = make_float4(a, cs, sn, 0.0f);
            else            sColV[buf][ww] = make_float4(a, cs, sn, 0.0f);
        }
        if (tid < 32) {
            float a = sWy[tid] * tr.yq;
            float sn, cs;
            sincosf(-TWO_PI * a, &sn, &cs);
            sColP[buf][tid] = make_float2(cs, sn);
        }
        __syncthreads();   // single barrier per triangle (double buffered)

        // ---- evaluate 8 points with no sincos ----
        const float area    = tr.area;
        const float twoArea = 2.0f * area;
        const float4 cU = sColU[buf][w];
        const float4 cV = sColV[buf][w];
        const float2 cP = sColP[buf][w];

#pragma unroll
        for (int k = 0; k < PPT; k++) {
            const int h = hbase + k;            // uniform across the warp
            const float4 rU = sRowU[buf][h];
            const float4 rV = sRowV[buf][h];
            const float2 rP = sRowP[buf][h];

            const float U_ = rU.x + cU.x;
            const float V_ = rV.x + cV.x;
            const float S  = U_ + V_;

            // three complex exponentials via products of unit phasors
            const float cu = rU.y * cU.y - rU.z * cU.z;
            const float su = rU.y * cU.z + rU.z * cU.y;
            const float cv = rV.y * cV.y - rV.z * cV.z;
            const float sv = rV.y * cV.z + rV.z * cV.y;
            const float c0 = rP.x * cP.x - rP.y * cP.y;
            const float s0 = rP.x * cP.y + rP.y * cP.x;

            float p2re, p2im, scale;
            if (U_ != 0.0f && V_ != 0.0f && S != 0.0f) {          // normal
                scale = __fdividef(twoArea, FOUR_PI2 * U_ * V_ * S);
                const float cuv = cu * cv - su * sv;
                const float suv = su * cv + cu * sv;
                p2re = -U_ * cuv + S * cu - V_;
                p2im = -U_ * suv + S * su;
            } else if (U_ == 0.0f && V_ == 0.0f) {                // zero
                accre[k] += area;
                continue;
            } else if (S == 0.0f) {                               // diag
                scale = -__fdividef(twoArea, FOUR_PI2 * U_ * U_);
                p2re = cu - 1.0f;
                p2im = su + TWO_PI * U_;
            } else if (U_ == 0.0f) {                              // u-mask
                scale = -__fdividef(twoArea, FOUR_PI2 * V_ * V_);
                p2re = cv - 1.0f;
                p2im = sv + TWO_PI * V_;
            } else {                                              // v-mask
                scale = __fdividef(twoArea, FOUR_PI2 * U_ * U_);
                const float t = TWO_PI * U_;
                p2re = cu - t * su - 1.0f;
                p2im = su + t * cu;
            }
            accre[k] += scale * (p2re * c0 - p2im * s0);
            accim[k] += scale * (p2re * s0 + p2im * c0);
        }
        // no second barrier: next iteration writes the OTHER buffer, and the
        // barrier at the top of the next iteration orders build(j+2) after
        // every thread's eval(j).
    }

#pragma unroll
    for (int k = 0; k < PPT; k++) {
        const int p = (hbase + k) * GW + w;
        g_partial[(b * NSPLIT + s) * NPTS + p] = make_float2(accre[k], accim[k]);
    }
}

__global__ __launch_bounds__(256)
void pfc_finalize_kernel(float* __restrict__ out) {
    const int idx = blockIdx.x * blockDim.x + threadIdx.x;   // 0 .. BATCH*NPTS-1
    if (idx >= BATCH * NPTS) return;
    const int b = idx / NPTS;
    const int p = idx % NPTS;
    const int h = p >> 5;

    float re = 0.0f, im = 0.0f;
#pragma unroll
    for (int s = 0; s < NSPLIT; s++) {
        float2 v = g_partial[(b * NSPLIT + s) * NPTS + p];
        re += v.x; im += v.y;
    }

    float mag, phase;
    const float m2 = re * re + im * im;
    if (h == GH - 1 || m2 == 0.0f) {      // padded row, or zero total
        mag = 0.0f; phase = 0.0f;
    } else {
        mag   = log1pf(sqrtf(m2));
        phase = atan2f(im, re);
    }
    out[idx] = mag;                        // mag  block: [B,1,GH,GW]
    out[BATCH * NPTS + idx] = phase;       // phase block: [B,1,GH,GW]
}

extern "C" void kernel_launch(void* const* d_in, const int* in_sizes, int n_in,
                              void* d_out, int out_size) {
    const float* tris    = (const float*)d_in[0];   // [64,128,3,2] f32
    const int*   lengths = (const int*)d_in[1];     // [64] i32
    float* out = (float*)d_out;                     // 262144 f32: mag then phase

    pfc_accum_kernel<<<BATCH * NSPLIT, NTHREADS>>>(tris, lengths);
    pfc_finalize_kernel<<<(BATCH * NPTS + 255) / 256, 256>>>(out);
}

// round 4
// speedup vs baseline: 2.3779x; 1.0430x over previous
#include <cuda_runtime.h>
#include <math.h>

#define BATCH   64
#define MAXN    128
#define GH      64
#define GW      32
#define NPTS    2048        // GH*GW
#define NSPLIT  16
#define MAXCHUNK 8          // ceil(MAXN / NSPLIT)
#define NTHREADS 256
#define PPT     8           // NPTS / NTHREADS

typedef unsigned long long u64;

// Partial accumulators: [BATCH][NSPLIT][NPTS] complex (float2) = 16 MB
__device__ float2 g_partial[BATCH * NSPLIT * NPTS];

// ---- packed f32x2 helpers ----
__device__ __forceinline__ u64 pk(float lo, float hi) {
    u64 r; asm("mov.b64 %0, {%1,%2};" : "=l"(r) : "f"(lo), "f"(hi)); return r;
}
__device__ __forceinline__ void upk(u64 v, float& lo, float& hi) {
    asm("mov.b64 {%0,%1}, %2;" : "=f"(lo), "=f"(hi) : "l"(v));
}
__device__ __forceinline__ u64 mul2(u64 a, u64 b) {
    u64 d; asm("mul.rn.f32x2 %0, %1, %2;" : "=l"(d) : "l"(a), "l"(b)); return d;
}
__device__ __forceinline__ u64 fma2(u64 a, u64 b, u64 c) {
    u64 d; asm("fma.rn.f32x2 %0, %1, %2, %3;" : "=l"(d) : "l"(a), "l"(b), "l"(c)); return d;
}
__device__ __forceinline__ u64 add2(u64 a, u64 b) {
    u64 d; asm("add.rn.f32x2 %0, %1, %2;" : "=l"(d) : "l"(a), "l"(b)); return d;
}

// pos_w[k] = float32(0.1 * (10^(1/30))^k), computed in double like numpy
__device__ __forceinline__ float pos_w_val(int k) {
    return (float)(0.1 * pow(10.0, (double)k / 30.0));
}

struct Tri { float xq, yq, xr, yr, xs, ys, area, scale2; };

__global__ __launch_bounds__(NTHREADS)
void pfc_accum_kernel(const float* __restrict__ tris,
                      const int* __restrict__ lengths) {
    __shared__ float sWx[GH];
    __shared__ float sWy[GW];
    __shared__ Tri   sTri[MAXCHUNK];
    // Row tables (per h): (cos, sin, -sin, lin). Q.lin = wx*dxr, R.lin = wx*dxs.
    __shared__ float4 sRowQ[2][GH], sRowR[2][GH], sRowS[2][GH];
    // Col tables (per w): (cos, sin, lin, 0). Q.lin = wy*dyr, R.lin = wy*dys.
    __shared__ float4 sColQ[2][GW], sColR[2][GW], sColS[2][GW];

    const int tid = threadIdx.x;
    const int b   = blockIdx.x >> 4;        // / NSPLIT
    const int s   = blockIdx.x & (NSPLIT - 1);

    // Build frequency grid (once per block)
    if (tid < GH) {
        int h = tid;
        float v;
        if (h < 31)       v = -pos_w_val(30 - h);
        else if (h == 31) v = 0.0f;
        else if (h <= 62) v = pos_w_val(h - 32);
        else              v = 0.0f;           // padded row
        sWx[h] = v;
    } else if (tid < GH + GW) {
        int w = tid - GH;
        sWy[w] = (w == 0) ? 0.0f : pos_w_val(w - 1);
    }

    const float TWO_PI   = 6.28318530717958648f;
    const float FOUR_PI2 = 4.0f * 3.14159274101257324f * 3.14159274101257324f;

    const int len  = lengths[b];
    // interleaved assignment: this split owns triangles s, s+16, s+32, ...
    const int ntri = (len > s) ? ((len - 1 - s) / NSPLIT + 1) : 0;

    if (tid < MAXCHUNK && tid < ntri) {
        const int t = s + tid * NSPLIT;
        const float* p = tris + (size_t)(b * MAXN + t) * 6;
        Tri tr;
        tr.xq = p[0]; tr.yq = p[1];
        tr.xr = p[2]; tr.yr = p[3];
        tr.xs = p[4]; tr.ys = p[5];
        float det = tr.xq * (tr.yr - tr.ys) + tr.xr * (tr.ys - tr.yq)
                  + tr.xs * (tr.yq - tr.yr);
        tr.area   = fabsf(0.5f * det);
        tr.scale2 = 2.0f * tr.area / FOUR_PI2;
        sTri[tid] = tr;
    }
    __syncthreads();

    const int w     = tid & 31;
    const int hbase = (tid >> 5) * PPT;

    u64 acc[PPT];
#pragma unroll
    for (int k = 0; k < PPT; k++) acc[k] = 0ull;

    for (int j = 0; j < ntri; j++) {
        const Tri tr = sTri[j];   // broadcast
        const int buf = j & 1;

        // ---- build factored vertex-phasor tables (288 sincos, coop) ----
        if (tid < 192) {
            int h = tid & 63;
            int which = tid >> 6;               // 0:Q 1:R 2:S
            float wx = sWx[h];
            float arg, lin;
            if (which == 0)      { arg = wx * tr.xq; lin = wx * (tr.xr - tr.xq); }
            else if (which == 1) { arg = wx * tr.xr; lin = wx * (tr.xs - tr.xr); }
            else                 { arg = wx * tr.xs; lin = 0.0f; }
            float sn, cs;
            sincosf(-TWO_PI * arg, &sn, &cs);
            float4 v = make_float4(cs, sn, -sn, lin);
            if (which == 0)      sRowQ[buf][h] = v;
            else if (which == 1) sRowR[buf][h] = v;
            else                 sRowS[buf][h] = v;
        } else {
            int ww = tid & 31;
            float wy = sWy[ww];
            float arg, lin;
            if (tid < 224) { arg = wy * tr.yq; lin = wy * (tr.yr - tr.yq); }
            else           { arg = wy * tr.yr; lin = wy * (tr.ys - tr.yr); }
            float sn, cs;
            sincosf(-TWO_PI * arg, &sn, &cs);
            float4 v = make_float4(cs, sn, lin, 0.0f);
            if (tid < 224) sColQ[buf][ww] = v;
            else           sColR[buf][ww] = v;
        }
        if (tid < 32) {                         // second job: colS
            float wy = sWy[tid];
            float sn, cs;
            sincosf(-TWO_PI * (wy * tr.ys), &sn, &cs);
            sColS[buf][tid] = make_float4(cs, sn, 0.0f, 0.0f);
        }
        __syncthreads();   // single barrier per triangle (double buffered)

        // ---- per-triangle column prep (done once, reused over 8 h's) ----
        const float4 cQ = sColQ[buf][w];
        const float4 cR = sColR[buf][w];
        const float4 cS = sColS[buf][w];
        const u64 cQcdN = pk(-cQ.x, -cQ.y);     // negated -> produces -Eq
        const u64 cQdcN = pk(-cQ.y, -cQ.x);
        const u64 cRcd  = pk( cR.x,  cR.y);     // positive -> Er
        const u64 cRdc  = pk( cR.y,  cR.x);
        const u64 cScdN = pk(-cS.x, -cS.y);     // negated -> -Es
        const u64 cSdcN = pk(-cS.y, -cS.x);
        const float cLinU = cQ.z;
        const float cLinV = cR.z;
        const float area   = tr.area;
        const float scale2 = tr.scale2;

#pragma unroll
        for (int k = 0; k < PPT; k++) {
            const int h = hbase + k;            // uniform across the warp
            const float4 rQ = sRowQ[buf][h];
            const float4 rR = sRowR[buf][h];
            const float4 rS = sRowS[buf][h];

            const float U_ = rQ.w + cLinU;
            const float V_ = rR.w + cLinV;
            const float S  = U_ + V_;

            // vertex phasors (row x col complex product), Q and S negated
            u64 EqN = mul2(pk(rQ.x, rQ.x), cQcdN);
            EqN     = fma2(pk(rQ.z, rQ.y), cQdcN, EqN);
            u64 Er  = mul2(pk(rR.x, rR.x), cRcd);
            Er      = fma2(pk(rR.z, rR.y), cRdc, Er);
            u64 EsN = mul2(pk(rS.x, rS.x), cScdN);
            EsN     = fma2(pk(rS.z, rS.y), cSdcN, EsN);

            if (U_ != 0.0f && V_ != 0.0f && S != 0.0f) {          // normal
                // p2 = -U_*Es + S*Er - V_*Eq  =  U_*EsN + S*Er + V_*EqN
                u64 p2 = mul2(pk(U_, U_), EsN);
                p2 = fma2(pk(S, S), Er, p2);
                p2 = fma2(pk(V_, V_), EqN, p2);
                const float scale = __fdividef(scale2, U_ * V_ * S);
                acc[k] = fma2(pk(scale, scale), p2, acc[k]);
            } else {
                float eqr, eqi, esr, esi, erre, erim;
                upk(EqN, eqr, eqi); eqr = -eqr; eqi = -eqi;
                upk(EsN, esr, esi); esr = -esr; esi = -esi;
                upk(Er, erre, erim);
                if (U_ == 0.0f && V_ == 0.0f) {                   // zero
                    acc[k] = add2(acc[k], pk(area, 0.0f));
                } else if (S == 0.0f) {                           // diag
                    const float scale = -__fdividef(scale2, U_ * U_);
                    const float wim = TWO_PI * U_;
                    const float tre = erre - eqr - wim * eqi;
                    const float tim = erim - eqi + wim * eqr;
                    acc[k] = fma2(pk(scale, scale), pk(tre, tim), acc[k]);
                } else if (U_ == 0.0f) {                          // u-mask
                    const float scale = -__fdividef(scale2, V_ * V_);
                    const float wim = TWO_PI * V_;
                    const float tre = esr - eqr - wim * eqi;
                    const float tim = esi - eqi + wim * eqr;
                    acc[k] = fma2(pk(scale, scale), pk(tre, tim), acc[k]);
                } else {                                          // v-mask
                    const float scale = __fdividef(scale2, U_ * U_);
                    const float wim = TWO_PI * U_;
                    const float tre = erre - wim * erim - eqr;
                    const float tim = erim + wim * erre - eqi;
                    acc[k] = fma2(pk(scale, scale), pk(tre, tim), acc[k]);
                }
            }
        }
        // no second barrier needed: next build writes the other buffer, and
        // the barrier at the top of iteration j+1 orders build(j+2) correctly.
    }

#pragma unroll
    for (int k = 0; k < PPT; k++) {
        const int p = (hbase + k) * GW + w;
        *reinterpret_cast<u64*>(&g_partial[(b * NSPLIT + s) * NPTS + p]) = acc[k];
    }
}

__global__ __launch_bounds__(256)
void pfc_finalize_kernel(float* __restrict__ out) {
    const int idx = blockIdx.x * blockDim.x + threadIdx.x;   // 0 .. BATCH*NPTS-1
    if (idx >= BATCH * NPTS) return;
    const int b = idx / NPTS;
    const int p = idx % NPTS;
    const int h = p >> 5;

    float re = 0.0f, im = 0.0f;
#pragma unroll
    for (int s = 0; s < NSPLIT; s++) {
        float2 v = g_partial[(b * NSPLIT + s) * NPTS + p];
        re += v.x; im += v.y;
    }

    float mag, phase;
    const float m2 = re * re + im * im;
    if (h == GH - 1 || m2 == 0.0f) {      // padded row, or zero total
        mag = 0.0f; phase = 0.0f;
    } else {
        mag   = log1pf(sqrtf(m2));
        phase = atan2f(im, re);
    }
    out[idx] = mag;                        // mag  block: [B,1,GH,GW]
    out[BATCH * NPTS + idx] = phase;       // phase block: [B,1,GH,GW]
}

extern "C" void kernel_launch(void* const* d_in, const int* in_sizes, int n_in,
                              void* d_out, int out_size) {
    const float* tris    = (const float*)d_in[0];   // [64,128,3,2] f32
    const int*   lengths = (const int*)d_in[1];     // [64] i32
    float* out = (float*)d_out;                     // 262144 f32: mag then phase

    pfc_accum_kernel<<<BATCH * NSPLIT, NTHREADS>>>(tris, lengths);
    pfc_finalize_kernel<<<(BATCH * NPTS + 255) / 256, 256>>>(out);
}